// round 3
// baseline (speedup 1.0000x reference)
#include <cuda_runtime.h>
#include <cuda_bf16.h>

// MaskedPooling: out[b,d] = sum_t x[b,t,d]*keep[b,t] / sum_t keep[b,t]
// keep = !mask (mask nonzero = excluded). x: [32,4096,512] f32, mask: [32,4096] int32.
// K1: per-(b, T-chunk) partial sums, skipping masked rows (saves ~50% HBM reads).
// K2: reduce partials + divide.

#define B_DIM 32
#define T_DIM 4096
#define D_DIM 512
#define S_SPLIT 16
#define ROWS (T_DIM / S_SPLIT)   // 256
#define TPB 128                  // 128 threads * float4 = 512 floats = D

__device__ float g_partial[B_DIM * S_SPLIT * D_DIM];  // 1 MB scratch
__device__ float g_count[B_DIM * S_SPLIT];

__global__ __launch_bounds__(TPB) void mp_partial_kernel(
    const float* __restrict__ x, const int* __restrict__ mask) {
    const int s = blockIdx.x;   // T-chunk
    const int b = blockIdx.y;   // batch
    const int tid = threadIdx.x;
    const int t0 = s * ROWS;

    __shared__ int m[ROWS];
    // stage mask chunk (256 int32 = 1 KB) in smem
    {
        const int4* msrc = reinterpret_cast<const int4*>(mask + b * T_DIM + t0);
        int4* mdst = reinterpret_cast<int4*>(m);
        for (int i = tid; i < ROWS / 4; i += TPB) mdst[i] = msrc[i];
    }
    __syncthreads();

    const float4* xp = reinterpret_cast<const float4*>(
        x + ((size_t)b * T_DIM + t0) * D_DIM);
    const int dstride = D_DIM / 4;  // 128 float4 per row

    float4 acc = make_float4(0.f, 0.f, 0.f, 0.f);
    int cnt = 0;
    #pragma unroll 4
    for (int t = 0; t < ROWS; t++) {
        if (m[t] == 0) {
            float4 v = xp[(size_t)t * dstride + tid];
            acc.x += v.x; acc.y += v.y; acc.z += v.z; acc.w += v.w;
            cnt++;
        }
    }

    reinterpret_cast<float4*>(g_partial)[(size_t)(b * S_SPLIT + s) * dstride + tid] = acc;
    if (tid == 0) g_count[b * S_SPLIT + s] = (float)cnt;
}

__global__ __launch_bounds__(TPB) void mp_finalize_kernel(float* __restrict__ out) {
    const int b = blockIdx.x;
    const int tid = threadIdx.x;
    const int dstride = D_DIM / 4;

    float denom = 0.f;
    #pragma unroll
    for (int s = 0; s < S_SPLIT; s++) denom += g_count[b * S_SPLIT + s];

    float4 acc = make_float4(0.f, 0.f, 0.f, 0.f);
    const float4* gp = reinterpret_cast<const float4*>(g_partial);
    #pragma unroll
    for (int s = 0; s < S_SPLIT; s++) {
        float4 v = gp[(size_t)(b * S_SPLIT + s) * dstride + tid];
        acc.x += v.x; acc.y += v.y; acc.z += v.z; acc.w += v.w;
    }
    float inv = 1.f / denom;
    acc.x *= inv; acc.y *= inv; acc.z *= inv; acc.w *= inv;
    reinterpret_cast<float4*>(out)[(size_t)b * dstride + tid] = acc;
}

extern "C" void kernel_launch(void* const* d_in, const int* in_sizes, int n_in,
                              void* d_out, int out_size) {
    const float* x = (const float*)d_in[0];
    const int* mask = (const int*)d_in[1];
    float* out = (float*)d_out;

    dim3 grid1(S_SPLIT, B_DIM);
    mp_partial_kernel<<<grid1, TPB>>>(x, mask);
    mp_finalize_kernel<<<B_DIM, TPB>>>(out);
}

// round 4
// speedup vs baseline: 1.5587x; 1.5587x over previous
#include <cuda_runtime.h>
#include <cuda_bf16.h>

// MaskedPooling: out[b,d] = sum_t x[b,t,d]*keep[b,t] / sum_t keep[b,t]
// x: [32,4096,512] f32, mask: [32,4096] int32 (nonzero = excluded).
// Single kernel: per-(b, T-chunk) CTA compacts kept-row indices (branch-free
// mainloop, MLP=8), writes partial sums; last CTA per batch fuses the final
// reduction (threadfence + semaphore) -> no second launch.

#define B_DIM 32
#define T_DIM 4096
#define D_DIM 512
#define S_SPLIT 16
#define ROWS (T_DIM / S_SPLIT)   // 256
#define TPB 128                  // 128 threads * float4 = 512 floats = D
#define DSTRIDE (D_DIM / 4)      // 128 float4 per row

__device__ float g_partial[B_DIM * S_SPLIT * D_DIM];  // 1 MB scratch
__device__ float g_count[B_DIM * S_SPLIT];
__device__ int   g_sem[B_DIM];                        // zero-init; self-resetting

__global__ __launch_bounds__(TPB) void mp_fused_kernel(
    const float* __restrict__ x, const int* __restrict__ mask,
    float* __restrict__ out) {
    const int s = blockIdx.x;   // T-chunk
    const int b = blockIdx.y;   // batch
    const int tid = threadIdx.x;
    const int lane = tid & 31;
    const int wid = tid >> 5;
    const int t0 = s * ROWS;

    __shared__ int m[ROWS];
    __shared__ short idxbuf[ROWS];
    __shared__ int wcnt[9];
    __shared__ bool isLast;

    // stage mask chunk (256 int32 = 1 KB)
    {
        const int4* msrc = reinterpret_cast<const int4*>(mask + b * T_DIM + t0);
        int4* mdst = reinterpret_cast<int4*>(m);
        for (int i = tid; i < ROWS / 4; i += TPB) mdst[i] = msrc[i];
    }
    __syncthreads();

    // compact kept-row indices: ballot + prefix popc, 2 rounds of 128 rows
    unsigned bal[2];
    bool kflag[2];
    #pragma unroll
    for (int r = 0; r < 2; r++) {
        int row = r * TPB + tid;
        kflag[r] = (m[row] == 0);
        bal[r] = __ballot_sync(0xffffffffu, kflag[r]);
        if (lane == 0) wcnt[r * 4 + wid] = __popc(bal[r]);
    }
    __syncthreads();
    if (tid == 0) {
        int sum = 0;
        #pragma unroll
        for (int j = 0; j < 8; j++) { int c = wcnt[j]; wcnt[j] = sum; sum += c; }
        wcnt[8] = sum;
    }
    __syncthreads();
    const int nkeep = wcnt[8];
    #pragma unroll
    for (int r = 0; r < 2; r++) {
        if (kflag[r]) {
            int pos = wcnt[r * 4 + wid] + __popc(bal[r] & ((1u << lane) - 1u));
            idxbuf[pos] = (short)(r * TPB + tid);
        }
    }
    __syncthreads();

    // branch-free mainloop: 8 independent LDG.128 per iter
    const float4* xp = reinterpret_cast<const float4*>(
        x + ((size_t)b * T_DIM + t0) * D_DIM);

    float4 acc = make_float4(0.f, 0.f, 0.f, 0.f);
    int i = 0;
    for (; i + 8 <= nkeep; i += 8) {
        float4 v[8];
        #pragma unroll
        for (int j = 0; j < 8; j++) {
            int r = idxbuf[i + j];
            v[j] = xp[(size_t)r * DSTRIDE + tid];
        }
        #pragma unroll
        for (int j = 0; j < 8; j++) {
            acc.x += v[j].x; acc.y += v[j].y; acc.z += v[j].z; acc.w += v[j].w;
        }
    }
    for (; i < nkeep; i++) {
        int r = idxbuf[i];
        float4 v = xp[(size_t)r * DSTRIDE + tid];
        acc.x += v.x; acc.y += v.y; acc.z += v.z; acc.w += v.w;
    }

    reinterpret_cast<float4*>(g_partial)[(size_t)(b * S_SPLIT + s) * DSTRIDE + tid] = acc;
    if (tid == 0) g_count[b * S_SPLIT + s] = (float)nkeep;

    // fused final reduction: last CTA of this batch
    __threadfence();
    if (tid == 0) {
        int v = atomicAdd(&g_sem[b], 1);
        isLast = (v == S_SPLIT - 1);
    }
    __syncthreads();

    if (isLast) {
        float denom = 0.f;
        #pragma unroll
        for (int ss = 0; ss < S_SPLIT; ss++) denom += g_count[b * S_SPLIT + ss];

        float4 racc = make_float4(0.f, 0.f, 0.f, 0.f);
        const float4* gp = reinterpret_cast<const float4*>(g_partial);
        #pragma unroll
        for (int ss = 0; ss < S_SPLIT; ss++) {
            float4 v = gp[(size_t)(b * S_SPLIT + ss) * DSTRIDE + tid];
            racc.x += v.x; racc.y += v.y; racc.z += v.z; racc.w += v.w;
        }
        float inv = 1.f / denom;
        racc.x *= inv; racc.y *= inv; racc.z *= inv; racc.w *= inv;
        reinterpret_cast<float4*>(out)[(size_t)b * DSTRIDE + tid] = racc;

        if (tid == 0) g_sem[b] = 0;  // reset for next graph replay
    }
}

extern "C" void kernel_launch(void* const* d_in, const int* in_sizes, int n_in,
                              void* d_out, int out_size) {
    const float* x = (const float*)d_in[0];
    const int* mask = (const int*)d_in[1];
    float* out = (float*)d_out;

    dim3 grid(S_SPLIT, B_DIM);
    mp_fused_kernel<<<grid, TPB>>>(x, mask, out);
}

// round 8
// speedup vs baseline: 1.6559x; 1.0624x over previous
#include <cuda_runtime.h>
#include <cuda_bf16.h>

// MaskedPooling: out[b,d] = sum_t x[b,t,d]*keep[b,t] / sum_t keep[b,t]
// x: [32,4096,512] f32, mask: [32,4096] int32 (nonzero = excluded).
// 1024 CTAs: per-(b, T-chunk of 128 rows) compaction + branch-free MLP=16
// mainloop; last CTA per batch fuses the final reduction.
// R7 fix: __syncthreads() BEFORE threadfence/semaphore so ALL warps' partial
// stores are complete before this CTA arrives (R6 raced: 1 stale partial/32).

#define B_DIM 32
#define T_DIM 4096
#define D_DIM 512
#define S_SPLIT 32
#define ROWS (T_DIM / S_SPLIT)   // 128
#define TPB 128                  // 128 threads * float4 = 512 floats = D
#define DSTRIDE (D_DIM / 4)      // 128 float4 per row

__device__ float g_partial[B_DIM * S_SPLIT * D_DIM];  // 2 MB scratch
__device__ float g_count[B_DIM * S_SPLIT];
__device__ int   g_sem[B_DIM];                        // zero-init; self-resetting

__global__ __launch_bounds__(TPB) void mp_fused_kernel(
    const float* __restrict__ x, const int* __restrict__ mask,
    float* __restrict__ out) {
    const int s = blockIdx.x;   // T-chunk
    const int b = blockIdx.y;   // batch
    const int tid = threadIdx.x;
    const int lane = tid & 31;
    const int wid = tid >> 5;
    const int t0 = s * ROWS;

    __shared__ int m[ROWS];
    __shared__ short idxbuf[ROWS];
    __shared__ int wcnt[5];
    __shared__ bool isLast;

    // stage mask chunk (128 int32 = 512 B)
    {
        const int4* msrc = reinterpret_cast<const int4*>(mask + b * T_DIM + t0);
        int4* mdst = reinterpret_cast<int4*>(m);
        if (tid < ROWS / 4) mdst[tid] = msrc[tid];
    }
    __syncthreads();

    // compact kept-row indices: single ballot round (ROWS == TPB)
    bool kflag = (m[tid] == 0);
    unsigned bal = __ballot_sync(0xffffffffu, kflag);
    if (lane == 0) wcnt[wid] = __popc(bal);
    __syncthreads();
    if (tid == 0) {
        int sum = 0;
        #pragma unroll
        for (int j = 0; j < 4; j++) { int c = wcnt[j]; wcnt[j] = sum; sum += c; }
        wcnt[4] = sum;
    }
    __syncthreads();
    const int nkeep = wcnt[4];
    if (kflag) {
        int pos = wcnt[wid] + __popc(bal & ((1u << lane) - 1u));
        idxbuf[pos] = (short)tid;
    }
    __syncthreads();

    // branch-free mainloop: 16 independent LDG.128 per iter, 2 accumulators
    const float4* xp = reinterpret_cast<const float4*>(
        x + ((size_t)b * T_DIM + t0) * D_DIM);

    float4 acc0 = make_float4(0.f, 0.f, 0.f, 0.f);
    float4 acc1 = make_float4(0.f, 0.f, 0.f, 0.f);
    int i = 0;
    for (; i + 16 <= nkeep; i += 16) {
        float4 v[16];
        #pragma unroll
        for (int j = 0; j < 16; j++) {
            int r = idxbuf[i + j];
            v[j] = xp[(size_t)r * DSTRIDE + tid];
        }
        #pragma unroll
        for (int j = 0; j < 16; j += 2) {
            acc0.x += v[j].x; acc0.y += v[j].y; acc0.z += v[j].z; acc0.w += v[j].w;
            acc1.x += v[j+1].x; acc1.y += v[j+1].y; acc1.z += v[j+1].z; acc1.w += v[j+1].w;
        }
    }
    for (; i + 4 <= nkeep; i += 4) {
        float4 v[4];
        #pragma unroll
        for (int j = 0; j < 4; j++) {
            int r = idxbuf[i + j];
            v[j] = xp[(size_t)r * DSTRIDE + tid];
        }
        #pragma unroll
        for (int j = 0; j < 4; j += 2) {
            acc0.x += v[j].x; acc0.y += v[j].y; acc0.z += v[j].z; acc0.w += v[j].w;
            acc1.x += v[j+1].x; acc1.y += v[j+1].y; acc1.z += v[j+1].z; acc1.w += v[j+1].w;
        }
    }
    for (; i < nkeep; i++) {
        int r = idxbuf[i];
        float4 v = xp[(size_t)r * DSTRIDE + tid];
        acc0.x += v.x; acc0.y += v.y; acc0.z += v.z; acc0.w += v.w;
    }
    acc0.x += acc1.x; acc0.y += acc1.y; acc0.z += acc1.z; acc0.w += acc1.w;

    reinterpret_cast<float4*>(g_partial)[(size_t)(b * S_SPLIT + s) * DSTRIDE + tid] = acc0;
    if (tid == 0) g_count[b * S_SPLIT + s] = (float)nkeep;

    // ALL warps must finish their partial stores before this CTA arrives.
    __syncthreads();
    __threadfence();
    if (tid == 0) {
        int v = atomicAdd(&g_sem[b], 1);
        isLast = (v == S_SPLIT - 1);
    }
    __syncthreads();

    if (isLast) {
        float denom = 0.f;
        #pragma unroll
        for (int ss = 0; ss < S_SPLIT; ss++) denom += g_count[b * S_SPLIT + ss];

        float4 r0 = make_float4(0.f, 0.f, 0.f, 0.f);
        float4 r1 = make_float4(0.f, 0.f, 0.f, 0.f);
        const float4* gp = reinterpret_cast<const float4*>(g_partial);
        #pragma unroll
        for (int ss = 0; ss < S_SPLIT; ss += 2) {
            float4 v0 = gp[(size_t)(b * S_SPLIT + ss) * DSTRIDE + tid];
            float4 v1 = gp[(size_t)(b * S_SPLIT + ss + 1) * DSTRIDE + tid];
            r0.x += v0.x; r0.y += v0.y; r0.z += v0.z; r0.w += v0.w;
            r1.x += v1.x; r1.y += v1.y; r1.z += v1.z; r1.w += v1.w;
        }
        r0.x += r1.x; r0.y += r1.y; r0.z += r1.z; r0.w += r1.w;
        float inv = 1.f / denom;
        r0.x *= inv; r0.y *= inv; r0.z *= inv; r0.w *= inv;
        reinterpret_cast<float4*>(out)[(size_t)b * DSTRIDE + tid] = r0;

        if (tid == 0) g_sem[b] = 0;  // reset for next graph replay
    }
}

extern "C" void kernel_launch(void* const* d_in, const int* in_sizes, int n_in,
                              void* d_out, int out_size) {
    const float* x = (const float*)d_in[0];
    const int* mask = (const int*)d_in[1];
    float* out = (float*)d_out;

    dim3 grid(S_SPLIT, B_DIM);
    mp_fused_kernel<<<grid, TPB>>>(x, mask, out);
}